// round 2
// baseline (speedup 1.0000x reference)
#include <cuda_runtime.h>
#include <math.h>
#include <stdint.h>

#define BATCH 16
#define KBOX  128
#define NUMC  80
#define OH    128
#define OW    128
#define NB    (BATCH*KBOX)

// ---- decoded mask ----
__device__ int d_mask[NB];

// ---- per-box scratch (sorted order) ----
__device__ float d_bx1[NB], d_by1[NB], d_bx2[NB], d_by2[NB];
__device__ float d_i2sy[NB], d_i2sx[NB], d_coef[NB];
__device__ int   d_cls[NB], d_cx[NB], d_cy[NB], d_hr[NB], d_wr[NB], d_act[NB];

// ---- global accumulators ----
__device__ double d_acc_hm;   // sum(pos_loss + neg_loss)
__device__ double d_acc_whn;  // sum(losses * reg_weight)
__device__ double d_acc_rw;   // sum(reg_weight)
__device__ int    d_acc_np;   // num_pos

__global__ void zero_kernel() {
    d_acc_hm = 0.0; d_acc_whn = 0.0; d_acc_rw = 0.0; d_acc_np = 0;
}

// =====================================================================
// Kernel 0: dtype-sniffing mask decode.
// Safe reads only: first NB bytes are in-bounds for any dtype >= 1 byte.
//  - any byte > 1            -> float32 (1.0f = 00 00 80 3f)
//  - else nonzero byte at i%4!=0 -> uint8 bool
//  - else                    -> int32 0/1
// =====================================================================
__global__ void decode_mask_kernel(const void* __restrict__ mraw) {
    __shared__ int s_gt1, s_off4;
    const uint8_t* b8 = (const uint8_t*)mraw;
    int t = threadIdx.x;
    if (t == 0) { s_gt1 = 0; s_off4 = 0; }
    __syncthreads();
    int gt1 = 0, off4 = 0;
    for (int i = t; i < NB; i += blockDim.x) {
        uint8_t v = b8[i];
        gt1  |= (v > 1);
        off4 |= (v != 0) && ((i & 3) != 0);
    }
    if (gt1)  atomicOr(&s_gt1, 1);
    if (off4) atomicOr(&s_off4, 1);
    __syncthreads();
    int mode = s_gt1 ? 2 : (s_off4 ? 0 : 1); // 0=u8, 1=i32, 2=f32
    for (int i = t; i < NB; i += blockDim.x) {
        int v;
        if (mode == 0)      v = (b8[i] != 0);
        else if (mode == 1) v = (((const int*)mraw)[i] != 0);
        else                v = (((const float*)mraw)[i] != 0.0f);
        d_mask[i] = v;
    }
}

// =====================================================================
// Kernel 1: per-image sort + per-box derived params.  grid=(BATCH), 128 thr
// =====================================================================
__global__ void prep_kernel(const float* __restrict__ tgt) {
    int b = blockIdx.x;
    int k = threadIdx.x;
    __shared__ float skey[KBOX];
    __shared__ int   sperm[KBOX];
    __shared__ float s_al0;

    const float* t = tgt + (size_t)(b*KBOX + k)*5;
    float x1 = t[1], y1 = t[2], x2 = t[3], y2 = t[4];
    int valid = d_mask[b*KBOX + k];
    float area = (x2 - x1) * (y2 - y1);
    float key = valid ? logf(area) : -INFINITY;
    skey[k] = key;
    __syncthreads();

    // stable descending rank (ties -> ascending original index)
    int rank = 0;
#pragma unroll 8
    for (int j = 0; j < KBOX; j++) {
        float kj = skey[j];
        rank += (kj > key) || (kj == key && j < k);
    }
    sperm[rank] = k;
    __syncthreads();

    if (k == 0) {
        int o0 = sperm[0];
        s_al0 = d_mask[b*KBOX + o0] ? skey[o0] : 0.0f;
    }
    __syncthreads();

    // thread k handles sorted slot k
    int o = sperm[k];
    const float* to = tgt + (size_t)(b*KBOX + o)*5;
    float clsf = to[0];
    float ox1 = to[1], oy1 = to[2], ox2 = to[3], oy2 = to[4];
    int v = d_mask[b*KBOX + o];
    float keyo = skey[o];

    float fx1 = fminf(fmaxf(ox1 * 0.25f, 0.0f), (float)(OW-1));
    float fy1 = fminf(fmaxf(oy1 * 0.25f, 0.0f), (float)(OH-1));
    float fx2 = fminf(fmaxf(ox2 * 0.25f, 0.0f), (float)(OW-1));
    float fy2 = fminf(fmaxf(oy2 * 0.25f, 0.0f), (float)(OH-1));
    float feat_h = fy2 - fy1;
    float feat_w = fx2 - fx1;

    int cx = (int)(((ox1 + ox2) * 0.5f) * 0.25f);
    int cy = (int)(((oy1 + oy2) * 0.5f) * 0.25f);
    int hr = (int)((feat_h * 0.5f) * 0.54f);
    int wr = (int)((feat_w * 0.5f) * 0.54f);
    float sy = (float)(2*hr + 1) / 6.0f;
    float sx = (float)(2*wr + 1) / 6.0f;
    float i2sy = 1.0f / (2.0f * sy * sy);
    float i2sx = 1.0f / (2.0f * sx * sx);

    int act = v && (cx >= 0) && (cx < OW) && (cy >= 0) && (cy < OH);

    float divs = 0.0f;
    if (act) {
        float sgy = 0.0f, sgx = 0.0f;
        int y0 = max(0, cy - hr), y1b = min(OH-1, cy + hr);
        for (int yy = y0; yy <= y1b; yy++) {
            float d = (float)(yy - cy);
            sgy += __expf(-(d*d) * i2sy);
        }
        int xa = max(0, cx - wr), xb = min(OW-1, cx + wr);
        for (int xx = xa; xx <= xb; xx++) {
            float d = (float)(xx - cx);
            sgx += __expf(-(d*d) * i2sx);
        }
        divs = sgy * sgx;
    }
    float al = v ? keyo : 0.0f;
    float factor = 2.0f - al / (s_al0 + 1e-7f);
    float coef = act ? (factor / (divs + 1e-7f)) : 0.0f;

    int idx = b*KBOX + k;
    d_bx1[idx] = ox1; d_by1[idx] = oy1; d_bx2[idx] = ox2; d_by2[idx] = oy2;
    d_i2sy[idx] = i2sy; d_i2sx[idx] = i2sx; d_coef[idx] = coef;
    d_cls[idx] = (int)clsf; d_cx[idx] = cx; d_cy[idx] = cy;
    d_hr[idx] = hr; d_wr[idx] = wr; d_act[idx] = act;
}

// u(x) = log(1 - clip(sigmoid(x))) * clip(sigmoid(x))^2   (3 MUFU)
__device__ __forceinline__ float focal_neg_base(float xv, float& p_out) {
    float t = __expf(-xv);
    float p = __fdividef(1.0f, 1.0f + t);
    p = fminf(fmaxf(p, 1e-4f), 0.9999f);
    p_out = p;
    float omp = 1.0f - p;
    return __logf(omp) * p * p;
}

// =====================================================================
// Kernel 2: main fused loss.  grid=(OH, BATCH), 128 thr (thread = x)
// =====================================================================
__global__ void loss_kernel(const float* __restrict__ hm,
                            const float* __restrict__ wh) {
    int y = blockIdx.x, b = blockIdx.y, x = threadIdx.x;
    int m = threadIdx.x;

    __shared__ float sgy[KBOX];
    __shared__ float sx1[KBOX], sy1s[KBOX], sx2[KBOX], sy2s[KBOX];
    __shared__ float scoef[KBOX], si2sx[KBOX];
    __shared__ int   scx[KBOX], swr[KBOX], scls[KBOX];
    __shared__ int   slist[KBOX];
    __shared__ int   s_n;

    int base = b*KBOX + m;
    {
        float i2sy = d_i2sy[base];
        int cy = d_cy[base], hr = d_hr[base];
        int act = d_act[base];
        int dy = y - cy;
        int rowcov = act && (abs(dy) <= hr);
        sgy[m] = rowcov ? __expf(-(float)(dy*dy) * i2sy) : 0.0f;
        sx1[m] = d_bx1[base]; sy1s[m] = d_by1[base];
        sx2[m] = d_bx2[base]; sy2s[m] = d_by2[base];
        scoef[m] = d_coef[base]; si2sx[m] = d_i2sx[base];
        scx[m] = d_cx[base]; swr[m] = d_wr[base]; scls[m] = d_cls[base];
    }
    __syncthreads();
    if (threadIdx.x == 0) {
        int n = 0;
        for (int j = 0; j < KBOX; j++)
            if (sgy[j] > 0.0f) slist[n++] = j;
        s_n = n;
    }
    __syncthreads();
    int n = s_n;

    // ---- coverage mask + winner (largest sorted index covering pixel) ----
    unsigned int covm[4] = {0u,0u,0u,0u};
    int e_w = -1;
    for (int e = 0; e < n; e++) {
        int j = slist[e];
        int dx = x - scx[j];
        if (abs(dx) <= swr[j]) {
            covm[e >> 5] |= 1u << (e & 31);
            e_w = e;
        }
    }

    float lsum = 0.0f;
    int   lnp = 0;

    // ---- focal base term over all classes ----
    const float* hmr = hm + (((size_t)b*NUMC)*OH + y)*OW + x;
#pragma unroll 4
    for (int c = 0; c < NUMC; c++) {
        float xv = hmr[(size_t)c * (OH*OW)];
        float p;
        lsum += focal_neg_base(xv, p);
    }

    // ---- footprint corrections ----
    for (int e = 0; e < n; e++) {
        if (!((covm[e >> 5] >> (e & 31)) & 1u)) continue;
        int j = slist[e];
        int c = scls[j];
        float dxf = (float)(x - scx[j]);
        float g = sgy[j] * __expf(-dxf*dxf * si2sx[j]);
        // representative: max g among same-class covering boxes (tie -> lowest e)
        bool rep = true;
        for (int e2 = 0; e2 < n; e2++) {
            if (e2 == e) continue;
            if (!((covm[e2 >> 5] >> (e2 & 31)) & 1u)) continue;
            int j2 = slist[e2];
            if (scls[j2] != c) continue;
            float dx2 = (float)(x - scx[j2]);
            float g2 = sgy[j2] * __expf(-dx2*dx2 * si2sx[j2]);
            if (g2 > g || (g2 == g && e2 < e)) { rep = false; break; }
        }
        if (!rep) continue;
        float xv = hmr[(size_t)c * (OH*OW)];
        float p;
        float u = focal_neg_base(xv, p);
        if (g == 1.0f) {
            float omp = 1.0f - p;
            float v = __logf(p) * omp * omp;   // pos term
            lsum += v - u;
            lnp++;
        } else {
            float omh = 1.0f - g;
            float w4 = omh * omh; w4 *= w4;    // (1-h)^4
            lsum += u * (w4 - 1.0f);
        }
    }

    // ---- wh / GIoU branch at winner pixels ----
    float lwhn = 0.0f, lrw = 0.0f;
    if (e_w >= 0) {
        int j = slist[e_w];
        float dxf = (float)(x - scx[j]);
        float g = sgy[j] * __expf(-dxf*dxf * si2sx[j]);
        float rw = g * scoef[j];
        size_t pbase = (((size_t)b*4)*OH + y)*OW + x;
        float pl = wh[pbase              ] * 16.0f;
        float pt = wh[pbase +   (OH*OW)  ] * 16.0f;
        float pr = wh[pbase + 2*(OH*OW)  ] * 16.0f;
        float pb = wh[pbase + 3*(OH*OW)  ] * 16.0f;
        float xs = (float)x * 4.0f, ys = (float)y * 4.0f;
        float tl = xs - sx1[j];
        float tt = ys - sy1s[j];
        float tr = sx2[j] - xs;
        float tb = sy2s[j] - ys;
        float ta = (tl + tr) * (tt + tb);
        float pa = (pl + pr) * (pt + pb);
        float wi = fminf(pl, tl) + fminf(pr, tr);
        float hi = fminf(pt, tt) + fminf(pb, tb);
        float ai = wi * hi;
        float au = ta + pa - ai;
        float iou = (ai + 1.0f) / (au + 1.0f);
        lwhn = (rw > 0.0f) ? (1.0f - iou) * rw : 0.0f;
        lrw = rw;
    }

    // ---- block reduce -> double atomics ----
    for (int off = 16; off; off >>= 1) {
        lsum += __shfl_down_sync(0xffffffffu, lsum, off);
        lwhn += __shfl_down_sync(0xffffffffu, lwhn, off);
        lrw  += __shfl_down_sync(0xffffffffu, lrw,  off);
        lnp  += __shfl_down_sync(0xffffffffu, lnp,  off);
    }
    __shared__ float r0[4], r1[4], r2[4];
    __shared__ int   r3[4];
    int wid = threadIdx.x >> 5;
    if ((threadIdx.x & 31) == 0) { r0[wid]=lsum; r1[wid]=lwhn; r2[wid]=lrw; r3[wid]=lnp; }
    __syncthreads();
    if (threadIdx.x == 0) {
        float a=0.f, c1=0.f, c2=0.f; int np=0;
        for (int i = 0; i < 4; i++) { a+=r0[i]; c1+=r1[i]; c2+=r2[i]; np+=r3[i]; }
        atomicAdd(&d_acc_hm,  (double)a);
        atomicAdd(&d_acc_whn, (double)c1);
        atomicAdd(&d_acc_rw,  (double)c2);
        atomicAdd(&d_acc_np,  np);
    }
}

__global__ void final_kernel(float* out) {
    double hm_sum = d_acc_hm;
    int np = d_acc_np;
    double hml;
    if (np > 0) hml = -hm_sum / (double)(np < 1 ? 1 : np);
    else        hml = -hm_sum;
    double whl = d_acc_whn / fmax(d_acc_rw, 1.0);
    out[0] = (float)(hml + whl);
}

extern "C" void kernel_launch(void* const* d_in, const int* in_sizes, int n_in,
                              void* d_out, int out_size) {
    const float* hm   = (const float*)d_in[0];
    const float* wh   = (const float*)d_in[1];
    const float* tgt  = (const float*)d_in[2];
    const void*  mask = (const void*)d_in[3];
    float* out = (float*)d_out;
    (void)in_sizes; (void)n_in; (void)out_size;

    zero_kernel<<<1, 1>>>();
    decode_mask_kernel<<<1, 256>>>(mask);
    prep_kernel<<<BATCH, KBOX>>>(tgt);
    loss_kernel<<<dim3(OH, BATCH), KBOX>>>(hm, wh);
    final_kernel<<<1, 1>>>(out);
}